// round 2
// baseline (speedup 1.0000x reference)
#include <cuda_runtime.h>
#include <math.h>

#define B_  8
#define S_  2048
#define H_  1024
#define D_  64
#define M_TOT (B_*S_)   // 16384

// Scratch for projected q, k, v (fp32): 3 x 4 MB. Device globals = legal scratch.
__device__ float g_q[M_TOT * D_];
__device__ float g_k[M_TOT * D_];
__device__ float g_v[M_TOT * D_];

typedef unsigned long long u64;

// ---- packed f32x2 helpers (sm_100+; doubles fp32 FMA throughput per pipe slot) ----
__device__ __forceinline__ u64 pk2(float x, float y) {
    u64 r; asm("mov.b64 %0, {%1, %2};" : "=l"(r) : "f"(x), "f"(y)); return r;
}
__device__ __forceinline__ void upk2(u64 v, float &x, float &y) {
    asm("mov.b64 {%0, %1}, %2;" : "=f"(x), "=f"(y) : "l"(v));
}
__device__ __forceinline__ void fma2(u64 &d, u64 a, u64 b) {
    asm("fma.rn.f32x2 %0, %1, %2, %0;" : "+l"(d) : "l"(a), "l"(b));
}
__device__ __forceinline__ void mul2(u64 &d, u64 a) {
    asm("mul.rn.f32x2 %0, %0, %1;" : "+l"(d) : "l"(a));
}

// ============================================================================
// QKV projection: out = x @ W + b for W in {Wq,Wk,Wv} (grid.y selects).
// BM=64 rows, BN=64 (full D), BK=32. 256 threads, 4x4 outputs/thread via f32x2.
// ============================================================================
__global__ void __launch_bounds__(256) qkv_kernel(
    const float* __restrict__ x,
    const float* __restrict__ Wq, const float* __restrict__ bq,
    const float* __restrict__ Wk, const float* __restrict__ bk,
    const float* __restrict__ Wv, const float* __restrict__ bv)
{
    const float* W; const float* bias; float* out;
    if (blockIdx.y == 0)      { W = Wq; bias = bq; out = g_q; }
    else if (blockIdx.y == 1) { W = Wk; bias = bk; out = g_k; }
    else                      { W = Wv; bias = bv; out = g_v; }

    __shared__ __align__(16) float Xs[32][68];  // [k][m], padded
    __shared__ __align__(16) float Ws[32][64];  // [k][n]

    const int tid = threadIdx.x;
    const int tx  = tid & 15;        // output col group (4 cols)
    const int ty  = tid >> 4;        // output row group (4 rows)
    const int mBase = blockIdx.x * 64;

    u64 acc[4][2];
    #pragma unroll
    for (int i = 0; i < 4; i++) { acc[i][0] = pk2(0.f, 0.f); acc[i][1] = pk2(0.f, 0.f); }

    const int lc4 = (tid & 7) * 4;   // k-offset for X loads
    const int lr  = tid >> 3;        // row for X loads (0..31)
    const int ln4 = (tid & 15) * 4;  // n-offset for W loads
    const int lk  = tid >> 4;        // k-row for W loads (0..15)

    for (int k0 = 0; k0 < H_; k0 += 32) {
        #pragma unroll
        for (int rr = 0; rr < 2; ++rr) {
            int row = lr + rr * 32;
            float4 v4 = *(const float4*)&x[(size_t)(mBase + row) * H_ + k0 + lc4];
            Xs[lc4 + 0][row] = v4.x; Xs[lc4 + 1][row] = v4.y;
            Xs[lc4 + 2][row] = v4.z; Xs[lc4 + 3][row] = v4.w;
        }
        #pragma unroll
        for (int rr = 0; rr < 2; ++rr) {
            int kr = lk + rr * 16;
            *(float4*)&Ws[kr][ln4] = *(const float4*)&W[(size_t)(k0 + kr) * D_ + ln4];
        }
        __syncthreads();

        #pragma unroll
        for (int kk = 0; kk < 32; ++kk) {
            float4 a = *(const float4*)&Xs[kk][ty * 4];
            float4 b = *(const float4*)&Ws[kk][tx * 4];
            u64 b01 = pk2(b.x, b.y), b23 = pk2(b.z, b.w);
            u64 a0 = pk2(a.x, a.x), a1 = pk2(a.y, a.y);
            u64 a2 = pk2(a.z, a.z), a3 = pk2(a.w, a.w);
            fma2(acc[0][0], a0, b01); fma2(acc[0][1], a0, b23);
            fma2(acc[1][0], a1, b01); fma2(acc[1][1], a1, b23);
            fma2(acc[2][0], a2, b01); fma2(acc[2][1], a2, b23);
            fma2(acc[3][0], a3, b01); fma2(acc[3][1], a3, b23);
        }
        __syncthreads();
    }

    #pragma unroll
    for (int i = 0; i < 4; i++) {
        float c0, c1, c2, c3;
        upk2(acc[i][0], c0, c1); upk2(acc[i][1], c2, c3);
        int row = mBase + ty * 4 + i;
        int col = tx * 4;
        float4 o;
        o.x = c0 + bias[col + 0]; o.y = c1 + bias[col + 1];
        o.z = c2 + bias[col + 2]; o.w = c3 + bias[col + 3];
        *(float4*)&out[(size_t)row * D_ + col] = o;
    }
}

// ============================================================================
// Causal attention, flash-style online softmax, fp32 + f32x2 packed FMA.
// 64 threads/CTA, 1 thread = 1 query row; 64-key tiles; K/V/S in smem (48 KB).
// out = (softmax(QK^T masked) / 32) @ V
// ============================================================================
__global__ void __launch_bounds__(64) attn_kernel(float* __restrict__ out)
{
    const int b  = blockIdx.y;
    const int xb = blockIdx.x;
    // Pair heavy/light m-blocks in launch order to smooth the causal imbalance.
    const int mIdx = (xb & 1) ? (31 - (xb >> 1)) : (xb >> 1);
    const int tid = threadIdx.x;
    const int row = mIdx * 64 + tid;

    __shared__ __align__(16) float Ks[64 * 64];
    __shared__ __align__(16) float Vs[64 * 64];
    __shared__ __align__(16) float Ss[64][64];  // scores, stored [key j][thread] => conflict-free

    // Q row in registers as 32 packed pairs
    u64 qp[32];
    {
        const float4* q4 = (const float4*)&g_q[((size_t)b * S_ + row) * D_];
        #pragma unroll
        for (int i = 0; i < 16; i++) {
            float4 v = q4[i];
            qp[2 * i]     = pk2(v.x, v.y);
            qp[2 * i + 1] = pk2(v.z, v.w);
        }
    }
    u64 o2[32];
    #pragma unroll
    for (int i = 0; i < 32; i++) o2[i] = pk2(0.f, 0.f);
    float mrun = -1e30f, lrun = 0.f;

    const float4* kg = (const float4*)&g_k[(size_t)b * S_ * D_];
    const float4* vg = (const float4*)&g_v[(size_t)b * S_ * D_];
    float4* ks4 = (float4*)Ks;
    float4* vs4 = (float4*)Vs;

    for (int t = 0; t <= mIdx; ++t) {
        __syncthreads();  // previous tile's smem reads done before overwrite
        const int base4 = t * 64 * 16;
        #pragma unroll
        for (int i = 0; i < 16; i++) {
            int id = i * 64 + tid;
            ks4[id] = kg[base4 + id];
            vs4[id] = vg[base4 + id];
        }
        __syncthreads();

        // ---- pass 1: s_j = q . k_j, track tile max, stage in smem ----
        float tmax = -1e30f;
        const bool diag = (t == mIdx);
        for (int j = 0; j < 64; ++j) {
            const float4* kr = (const float4*)&Ks[j * 64];
            u64 a0 = pk2(0.f, 0.f), a1 = pk2(0.f, 0.f);
            u64 a2 = pk2(0.f, 0.f), a3 = pk2(0.f, 0.f);
            #pragma unroll
            for (int i2 = 0; i2 < 16; i2 += 2) {
                float4 kv0 = kr[i2], kv1 = kr[i2 + 1];
                fma2(a0, qp[2 * i2],     pk2(kv0.x, kv0.y));
                fma2(a1, qp[2 * i2 + 1], pk2(kv0.z, kv0.w));
                fma2(a2, qp[2 * i2 + 2], pk2(kv1.x, kv1.y));
                fma2(a3, qp[2 * i2 + 3], pk2(kv1.z, kv1.w));
            }
            float s0, s1, s2, s3, s4, s5, s6, s7;
            upk2(a0, s0, s1); upk2(a1, s2, s3);
            upk2(a2, s4, s5); upk2(a3, s6, s7);
            float s = ((s0 + s1) + (s2 + s3)) + ((s4 + s5) + (s6 + s7));
            if (diag && j > tid) s = -1e30f;  // causal mask within diagonal tile
            tmax = fmaxf(tmax, s);
            Ss[j][tid] = s;
        }

        // ---- online softmax rescale ----
        float mnew = fmaxf(mrun, tmax);
        float corr = __expf(mrun - mnew);
        lrun *= corr;
        u64 corr2 = pk2(corr, corr);
        #pragma unroll
        for (int i = 0; i < 32; i++) mul2(o2[i], corr2);
        mrun = mnew;

        // ---- pass 2: p = exp(s - m), accumulate p * V ----
        for (int j = 0; j < 64; ++j) {
            float p = __expf(Ss[j][tid] - mnew);
            lrun += p;
            u64 p2 = pk2(p, p);
            const float4* vr = (const float4*)&Vs[j * 64];
            #pragma unroll
            for (int i2 = 0; i2 < 16; i2++) {
                float4 vv = vr[i2];
                fma2(o2[2 * i2],     p2, pk2(vv.x, vv.y));
                fma2(o2[2 * i2 + 1], p2, pk2(vv.z, vv.w));
            }
        }
    }

    // epilogue: /l (softmax normalize) and /sqrt(H)=32 (module's post-softmax scale)
    const float inv = 1.0f / (lrun * 32.0f);
    float* orow = &out[((size_t)b * S_ + row) * D_];
    #pragma unroll
    for (int i = 0; i < 16; i++) {
        float x0, x1, x2, x3;
        upk2(o2[2 * i], x0, x1);
        upk2(o2[2 * i + 1], x2, x3);
        float4 o = make_float4(x0 * inv, x1 * inv, x2 * inv, x3 * inv);
        *(float4*)&orow[i * 4] = o;
    }
}

extern "C" void kernel_launch(void* const* d_in, const int* in_sizes, int n_in,
                              void* d_out, int out_size)
{
    const float* x  = (const float*)d_in[0];
    const float* Wq = (const float*)d_in[1];
    const float* bq = (const float*)d_in[2];
    const float* Wk = (const float*)d_in[3];
    const float* bk = (const float*)d_in[4];
    const float* Wv = (const float*)d_in[5];
    const float* bv = (const float*)d_in[6];
    float* out = (float*)d_out;

    qkv_kernel<<<dim3(M_TOT / 64, 3), 256>>>(x, Wq, bq, Wk, bk, Wv, bv);
    attn_kernel<<<dim3(S_ / 64, B_), 64>>>(out);
}